// round 1
// baseline (speedup 1.0000x reference)
#include <cuda_runtime.h>
#include <cuda_bf16.h>
#include <math.h>

// Problem constants
#define BATCH   2
#define SEQLEN  2048
#define DMODEL  1024
#define DINNER  2048
#define DSTATE  16
#define DCONV   4
#define DTRANK  64
#define XDBL    (DTRANK + 2*DSTATE)   // 160
#define MROWS   (BATCH*SEQLEN)        // 4096

// Scratch (device globals — no allocation allowed)
__device__ float g_xz  [MROWS * 2*DINNER];  // (b,l, 2*d_inner)  67MB
__device__ float g_xs  [MROWS * DINNER];    // conv+silu output  33.5MB
__device__ float g_xdbl[MROWS * XDBL];      // x_proj output
__device__ float g_dt  [MROWS * DINNER];    // softplus(dt)      33.5MB
__device__ float g_y   [MROWS * DINNER];    // scan output (gated) 33.5MB

// ---------------------------------------------------------------------------
// Generic fp32 GEMM:  C[M,N] = A[M,K] * W[N,K]^T   (both K-contiguous, "NT")
// BM=BN=64, BK=16, 256 threads, 4x4 micro-tile per thread.
// mode 0: plain store. mode 1: softplus(acc + bias[col]).
// M must be a multiple of 64 and K a multiple of 16 (true for all calls).
// ---------------------------------------------------------------------------
__global__ void gemm_nt(const float* __restrict__ A, int lda,
                        const float* __restrict__ W, int ldw,
                        float* __restrict__ C, int ldc,
                        int M, int N, int K,
                        const float* __restrict__ bias, int mode)
{
    __shared__ float As[16][64];
    __shared__ float Ws[16][64];

    const int tid = threadIdx.x;
    const int tx = tid & 15;        // 0..15 -> N direction (x4)
    const int ty = tid >> 4;        // 0..15 -> M direction (x4)
    const int rowBase = blockIdx.y * 64;
    const int colBase = blockIdx.x * 64;

    const int loadRow = tid >> 2;        // 0..63
    const int loadK   = (tid & 3) * 4;   // 0,4,8,12

    float acc[4][4];
#pragma unroll
    for (int i = 0; i < 4; i++)
#pragma unroll
        for (int j = 0; j < 4; j++) acc[i][j] = 0.f;

    for (int k0 = 0; k0 < K; k0 += 16) {
        // A tile: rows always in-bounds (M % 64 == 0)
        float4 av = *(const float4*)(A + (size_t)(rowBase + loadRow) * lda + k0 + loadK);
        As[loadK + 0][loadRow] = av.x;
        As[loadK + 1][loadRow] = av.y;
        As[loadK + 2][loadRow] = av.z;
        As[loadK + 3][loadRow] = av.w;

        // W tile: guard N edge
        int wr = colBase + loadRow;
        float4 wv = make_float4(0.f, 0.f, 0.f, 0.f);
        if (wr < N)
            wv = *(const float4*)(W + (size_t)wr * ldw + k0 + loadK);
        Ws[loadK + 0][loadRow] = wv.x;
        Ws[loadK + 1][loadRow] = wv.y;
        Ws[loadK + 2][loadRow] = wv.z;
        Ws[loadK + 3][loadRow] = wv.w;

        __syncthreads();

#pragma unroll
        for (int k = 0; k < 16; k++) {
            float4 a = *(const float4*)&As[k][ty * 4];
            float4 w = *(const float4*)&Ws[k][tx * 4];
            acc[0][0] += a.x * w.x; acc[0][1] += a.x * w.y; acc[0][2] += a.x * w.z; acc[0][3] += a.x * w.w;
            acc[1][0] += a.y * w.x; acc[1][1] += a.y * w.y; acc[1][2] += a.y * w.z; acc[1][3] += a.y * w.w;
            acc[2][0] += a.z * w.x; acc[2][1] += a.z * w.y; acc[2][2] += a.z * w.z; acc[2][3] += a.z * w.w;
            acc[3][0] += a.w * w.x; acc[3][1] += a.w * w.y; acc[3][2] += a.w * w.z; acc[3][3] += a.w * w.w;
        }
        __syncthreads();
    }

#pragma unroll
    for (int i = 0; i < 4; i++) {
        int r = rowBase + ty * 4 + i;
#pragma unroll
        for (int j = 0; j < 4; j++) {
            int c = colBase + tx * 4 + j;
            if (c < N) {
                float v = acc[i][j];
                if (mode == 1) {
                    v += bias[c];
                    v = (v > 20.f) ? v : log1pf(expf(v));   // softplus
                }
                C[(size_t)r * ldc + c] = v;
            }
        }
    }
}

// ---------------------------------------------------------------------------
// Depthwise causal conv (kernel 4) + bias + SiLU.
// Input: g_xz first DINNER channels of each (b,l) row. Output g_xs (b,l,d).
// ---------------------------------------------------------------------------
__global__ void conv_silu(const float* __restrict__ conv_w,
                          const float* __restrict__ conv_b)
{
    int idx = blockIdx.x * blockDim.x + threadIdx.x;
    if (idx >= MROWS * DINNER) return;
    int d = idx % DINNER;
    int l = (idx / DINNER) % SEQLEN;
    int b = idx / (DINNER * SEQLEN);

    float acc = conv_b[d];
    const float* xi = g_xz + ((size_t)b * SEQLEN) * (2 * DINNER) + d;
#pragma unroll
    for (int j = 0; j < DCONV; j++) {
        int ll = l - (DCONV - 1) + j;
        if (ll >= 0)
            acc += xi[(size_t)ll * (2 * DINNER)] * conv_w[d * DCONV + j];
    }
    // SiLU
    float s = acc / (1.f + __expf(-acc));
    g_xs[idx] = s;
}

// ---------------------------------------------------------------------------
// Selective scan. One warp handles 2 channels; 16 lanes per channel map the
// state dim. Loop-carried dep is one FFMA (h = dA*h + dBx). y reduced via
// shfl_xor over the 16 state lanes; fused with +xs*D and *silu(z).
// ---------------------------------------------------------------------------
__global__ void scan_kernel(const float* __restrict__ A_log,
                            const float* __restrict__ Dv)
{
    int gwarp = (blockIdx.x * blockDim.x + threadIdx.x) >> 5;
    int lane  = threadIdx.x & 31;
    int n     = lane & 15;          // state index
    int half  = lane >> 4;          // channel within warp
    int ch    = gwarp * 2 + half;   // 0 .. BATCH*DINNER-1
    if (ch >= BATCH * DINNER) return;
    int b = ch / DINNER;
    int d = ch % DINNER;

    float a  = -expf(A_log[d * DSTATE + n]);
    float Dd = Dv[d];
    float h  = 0.f;

    const float* dt_p = g_dt   + (size_t)b * SEQLEN * DINNER + d;
    const float* xs_p = g_xs   + (size_t)b * SEQLEN * DINNER + d;
    const float* B_p  = g_xdbl + (size_t)b * SEQLEN * XDBL + DTRANK + n;
    const float* C_p  = B_p + DSTATE;
    const float* z_p  = g_xz   + (size_t)b * SEQLEN * (2 * DINNER) + DINNER + d;
    float*       y_p  = g_y    + (size_t)b * SEQLEN * DINNER + d;

    for (int l = 0; l < SEQLEN; l++) {
        float dtv = __ldg(dt_p);
        float xv  = __ldg(xs_p);
        float Bv  = __ldg(B_p);
        float Cv  = __ldg(C_p);

        float dA = __expf(dtv * a);
        h = dA * h + (dtv * xv) * Bv;
        float yv = h * Cv;

        // sum over 16 state lanes (stays within each 16-lane half)
        yv += __shfl_xor_sync(0xFFFFFFFFu, yv, 8);
        yv += __shfl_xor_sync(0xFFFFFFFFu, yv, 4);
        yv += __shfl_xor_sync(0xFFFFFFFFu, yv, 2);
        yv += __shfl_xor_sync(0xFFFFFFFFu, yv, 1);

        if (n == 0) {
            float zv = __ldg(z_p);
            float gate = zv / (1.f + __expf(-zv));   // silu(z)
            *y_p = (yv + xv * Dd) * gate;
        }

        dt_p += DINNER;
        xs_p += DINNER;
        B_p  += XDBL;
        C_p  += XDBL;
        z_p  += 2 * DINNER;
        y_p  += DINNER;
    }
}

// ---------------------------------------------------------------------------
extern "C" void kernel_launch(void* const* d_in, const int* in_sizes, int n_in,
                              void* d_out, int out_size)
{
    const float* x         = (const float*)d_in[0];
    const float* in_proj_w = (const float*)d_in[1];
    const float* conv_w    = (const float*)d_in[2];
    const float* conv_b    = (const float*)d_in[3];
    const float* x_proj_w  = (const float*)d_in[4];
    const float* dt_proj_w = (const float*)d_in[5];
    const float* dt_proj_b = (const float*)d_in[6];
    const float* A_log     = (const float*)d_in[7];
    const float* Dv        = (const float*)d_in[8];
    const float* out_proj_w= (const float*)d_in[9];
    float* out = (float*)d_out;

    float *xz, *xs, *xdbl, *dt, *y;
    cudaGetSymbolAddress((void**)&xz,   g_xz);
    cudaGetSymbolAddress((void**)&xs,   g_xs);
    cudaGetSymbolAddress((void**)&xdbl, g_xdbl);
    cudaGetSymbolAddress((void**)&dt,   g_dt);
    cudaGetSymbolAddress((void**)&y,    g_y);

    // 1) xz = x @ in_proj_w^T   (4096 x 4096, K=1024)
    gemm_nt<<<dim3(2*DINNER/64, MROWS/64), 256>>>(
        x, DMODEL, in_proj_w, DMODEL, xz, 2*DINNER,
        MROWS, 2*DINNER, DMODEL, nullptr, 0);

    // 2) depthwise conv + SiLU -> xs
    conv_silu<<<(MROWS*DINNER + 255)/256, 256>>>(conv_w, conv_b);

    // 3) x_dbl = xs @ x_proj_w^T   (4096 x 160, K=2048)
    gemm_nt<<<dim3((XDBL + 63)/64, MROWS/64), 256>>>(
        xs, DINNER, x_proj_w, DINNER, xdbl, XDBL,
        MROWS, XDBL, DINNER, nullptr, 0);

    // 4) dt = softplus(x_dbl[:, :64] @ dt_proj_w^T + dt_proj_b)  (4096 x 2048, K=64)
    gemm_nt<<<dim3(DINNER/64, MROWS/64), 256>>>(
        xdbl, XDBL, dt_proj_w, DTRANK, dt, DINNER,
        MROWS, DINNER, DTRANK, dt_proj_b, 1);

    // 5) selective scan + D skip + silu(z) gate -> y
    scan_kernel<<<(BATCH*DINNER/2)*32/256, 256>>>(A_log, Dv);

    // 6) out = y @ out_proj_w^T   (4096 x 1024, K=2048)
    gemm_nt<<<dim3(DMODEL/64, MROWS/64), 256>>>(
        y, DINNER, out_proj_w, DINNER, out, DMODEL,
        MROWS, DMODEL, DINNER, nullptr, 0);
}

// round 4
// speedup vs baseline: 1.2223x; 1.2223x over previous
#include <cuda_runtime.h>
#include <cuda_bf16.h>
#include <math.h>
#include <stdint.h>

// Problem constants
#define BATCH   2
#define SEQLEN  2048
#define DMODEL  1024
#define DINNER  2048
#define DSTATE  16
#define DCONV   4
#define DTRANK  64
#define XDBL    (DTRANK + 2*DSTATE)   // 160
#define MROWS   (BATCH*SEQLEN)        // 4096

// ---------------------------------------------------------------------------
// Device-global scratch (no allocation allowed)
// ---------------------------------------------------------------------------
__device__ float g_xz  [MROWS * 2*DINNER];   // in_proj output
__device__ float g_xs  [MROWS * DINNER];     // conv+silu output (fp32 for scan)
__device__ float g_xdbl[MROWS * XDBL];       // x_proj output
__device__ float g_dt  [MROWS * DINNER];     // softplus dt (fp32 for scan)

// Split-bf16 operands, K-interleaved:  A2 = [hi|hi|lo], B2 = [hi|lo|hi]
__device__ __nv_bfloat16 g_x2  [MROWS * 3*DMODEL];
__device__ __nv_bfloat16 g_w1_2[2*DINNER * 3*DMODEL];
__device__ __nv_bfloat16 g_xs2 [MROWS * 3*DINNER];
__device__ __nv_bfloat16 g_w3_2[XDBL * 3*DINNER];
__device__ __nv_bfloat16 g_dt2 [MROWS * 3*DTRANK];
__device__ __nv_bfloat16 g_w4_2[DINNER * 3*DTRANK];
__device__ __nv_bfloat16 g_y2  [MROWS * 3*DINNER];
__device__ __nv_bfloat16 g_w6_2[DMODEL * 3*DINNER];

// ---------------------------------------------------------------------------
// PTX helpers (baseline ISA only: cp.async, ldmatrix, mma.sync)
// ---------------------------------------------------------------------------
__device__ __forceinline__ uint32_t smem_u32(const void* p) {
    uint32_t a;
    asm("{ .reg .u64 t; cvta.to.shared.u64 t, %1; cvt.u32.u64 %0, t; }"
        : "=r"(a) : "l"(p));
    return a;
}

#define CP_ASYNC16(dst, src) \
    asm volatile("cp.async.cg.shared.global [%0], [%1], 16;" :: "r"(dst), "l"(src) : "memory")
#define CP_COMMIT() asm volatile("cp.async.commit_group;" ::: "memory")
#define CP_WAIT1()  asm volatile("cp.async.wait_group 1;" ::: "memory")

#define LDSM4(r, addr) \
    asm volatile("ldmatrix.sync.aligned.m8n8.x4.shared.b16 {%0,%1,%2,%3}, [%4];" \
        : "=r"((r)[0]), "=r"((r)[1]), "=r"((r)[2]), "=r"((r)[3]) : "r"(addr))

#define MMA16816(c, a, b) \
    asm volatile("mma.sync.aligned.m16n8k16.row.col.f32.bf16.bf16.f32 " \
        "{%0,%1,%2,%3}, {%4,%5,%6,%7}, {%8,%9}, {%0,%1,%2,%3};" \
        : "+f"((c)[0]), "+f"((c)[1]), "+f"((c)[2]), "+f"((c)[3]) \
        : "r"((a)[0]), "r"((a)[1]), "r"((a)[2]), "r"((a)[3]), \
          "r"((b)[0]), "r"((b)[1]))

// ---------------------------------------------------------------------------
// Tensor-core GEMM:  C[M, Nact] = A2[M, K2] * B2[Nact, K2]^T  (bf16 in, fp32 out)
// Block tile 128x128, BK=64 (128B rows), 8 warps as 2(M) x 4(N), warp 64x32.
// cp.async 2-stage pipeline, swizzled smem, ldmatrix + mma.sync.
// mode 0: plain store; mode 1: softplus(v + bias[col]).
// Requirements: M % 128 == 0, K2 % 64 == 0.
// ---------------------------------------------------------------------------
#define GEMM_SMEM (4 * 16384)

__global__ void __launch_bounds__(256, 2)
gemm_mma(const __nv_bfloat16* __restrict__ A2,
         const __nv_bfloat16* __restrict__ B2,
         float* __restrict__ C, int ldc, int K2, int Nact,
         const float* __restrict__ bias, int mode)
{
    extern __shared__ char smem[];
    const uint32_t sb = smem_u32(smem);
    const int tid  = threadIdx.x;
    const int wid  = tid >> 5;
    const int lane = tid & 31;
    const int wm   = wid >> 2;       // 0..1
    const int wn   = wid & 3;        // 0..3
    const int mBase = blockIdx.y * 128;
    const int nBase = blockIdx.x * 128;

    // per-thread cp.async source: row r = tid>>1, half = tid&1 (64B each)
    const int r    = tid >> 1;
    const int half = tid & 1;
    const __nv_bfloat16* aSrcRow = A2 + (size_t)(mBase + r) * K2;
    int brow = nBase + r; if (brow >= Nact) brow = Nact - 1;
    const __nv_bfloat16* bSrcRow = B2 + (size_t)brow * K2;
    const uint32_t dstRowOff = (uint32_t)r * 128;
    const uint32_t rxor = (uint32_t)(r & 7) << 4;

    const int nch = K2 >> 6;

#define ISSUE(c, buf) do {                                                    \
    const char* as = (const char*)aSrcRow + (size_t)(c) * 128 + half * 64;    \
    const char* bs = (const char*)bSrcRow + (size_t)(c) * 128 + half * 64;    \
    uint32_t abuf = sb + (uint32_t)(buf) * 32768;                             \
    uint32_t bbuf = abuf + 16384;                                             \
    _Pragma("unroll")                                                         \
    for (int u = 0; u < 4; u++) {                                             \
        uint32_t boff = (uint32_t)(half * 64 + u * 16) ^ rxor;                \
        CP_ASYNC16(abuf + dstRowOff + boff, as + u * 16);                     \
        CP_ASYNC16(bbuf + dstRowOff + boff, bs + u * 16);                     \
    }                                                                         \
} while (0)

    float acc[4][4][4];
#pragma unroll
    for (int i = 0; i < 4; i++)
#pragma unroll
        for (int j = 0; j < 4; j++)
#pragma unroll
            for (int k = 0; k < 4; k++) acc[i][j][k] = 0.f;

    // ldmatrix per-lane addressing
    const uint32_t lrow  = lane & 15;
    const uint32_t lsel  = (lane >> 4) * 16;          // 0 or 16 bytes (k-half)
    const uint32_t lxor  = (uint32_t)(lane & 7) << 4; // swizzle for addressed row

    ISSUE(0, 0); CP_COMMIT();
    if (nch > 1) ISSUE(1, 1);
    CP_COMMIT();

    for (int c = 0; c < nch; c++) {
        CP_WAIT1();
        __syncthreads();

        const uint32_t abuf = sb + (uint32_t)(c & 1) * 32768;
        const uint32_t bbuf = abuf + 16384;
        const uint32_t aRow = abuf + (wm * 64 + lrow) * 128;
        const uint32_t bRow = bbuf + (wn * 32 + lrow) * 128;

#pragma unroll
        for (int s = 0; s < 4; s++) {
            const uint32_t kb = ((uint32_t)(s * 32) + lsel) ^ lxor;
            uint32_t aF[4][4];
            uint32_t bF[4][2];
#pragma unroll
            for (int mt = 0; mt < 4; mt++)
                LDSM4(aF[mt], aRow + mt * 2048 + kb);
#pragma unroll
            for (int nh = 0; nh < 2; nh++) {
                uint32_t t[4];
                LDSM4(t, bRow + nh * 2048 + kb);
                // ldmatrix x4 order: t0=(n0-7,kL) t1=(n8-15,kL) t2=(n0-7,kH) t3=(n8-15,kH)
                // B fragment per n8 tile = {kL, kH}:
                bF[nh * 2 + 0][0] = t[0]; bF[nh * 2 + 0][1] = t[2];
                bF[nh * 2 + 1][0] = t[1]; bF[nh * 2 + 1][1] = t[3];
            }
#pragma unroll
            for (int mt = 0; mt < 4; mt++)
#pragma unroll
                for (int nt = 0; nt < 4; nt++)
                    MMA16816(acc[mt][nt], aF[mt], bF[nt]);
        }
        __syncthreads();
        if (c + 2 < nch) ISSUE(c + 2, c & 1);
        CP_COMMIT();
    }

    // Epilogue
    const int er0 = mBase + wm * 64 + (lane >> 2);
    const int ec0 = nBase + wn * 32 + (lane & 3) * 2;
#pragma unroll
    for (int mt = 0; mt < 4; mt++) {
#pragma unroll
        for (int nt = 0; nt < 4; nt++) {
            int col = ec0 + nt * 8;
#pragma unroll
            for (int h = 0; h < 2; h++) {          // h=0: row, h=1: row+8
                int row = er0 + mt * 16 + h * 8;
                float v0 = acc[mt][nt][h * 2 + 0];
                float v1 = acc[mt][nt][h * 2 + 1];
                if (mode == 1) {
                    if (col < Nact) {
                        v0 += bias[col];
                        v0 = (v0 > 20.f) ? v0 : log1pf(expf(v0));
                    }
                    if (col + 1 < Nact) {
                        v1 += bias[col + 1];
                        v1 = (v1 > 20.f) ? v1 : log1pf(expf(v1));
                    }
                }
                float* cp = C + (size_t)row * ldc + col;
                if (col + 1 < Nact) { cp[0] = v0; cp[1] = v1; }
                else if (col < Nact) { cp[0] = v0; }
            }
        }
    }
#undef ISSUE
}

// ---------------------------------------------------------------------------
// Split kernels: fp32 -> K-interleaved bf16 operand layouts
// A-type: out[r, c]=hi, out[r, K+c]=hi, out[r, 2K+c]=lo
// B-type: out[r, c]=hi, out[r, K+c]=lo, out[r, 2K+c]=hi
// ---------------------------------------------------------------------------
__global__ void split_A(const float* __restrict__ in, __nv_bfloat16* __restrict__ out,
                        int K, int total)
{
    int i = blockIdx.x * blockDim.x + threadIdx.x;
    if (i >= total) return;
    int r = i / K, c = i - r * K;
    float v = in[i];
    __nv_bfloat16 h = __float2bfloat16(v);
    __nv_bfloat16 l = __float2bfloat16(v - __bfloat162float(h));
    __nv_bfloat16* o = out + (size_t)r * 3 * K + c;
    o[0] = h; o[K] = h; o[2 * K] = l;
}

__global__ void split_B(const float* __restrict__ in, __nv_bfloat16* __restrict__ out,
                        int K, int total)
{
    int i = blockIdx.x * blockDim.x + threadIdx.x;
    if (i >= total) return;
    int r = i / K, c = i - r * K;
    float v = in[i];
    __nv_bfloat16 h = __float2bfloat16(v);
    __nv_bfloat16 l = __float2bfloat16(v - __bfloat162float(h));
    __nv_bfloat16* o = out + (size_t)r * 3 * K + c;
    o[0] = h; o[K] = l; o[2 * K] = h;
}

// x_dbl[:, :DTRANK] (stride XDBL) -> g_dt2 [MROWS, 3*DTRANK] A-type
__global__ void split_dtrank()
{
    int i = blockIdx.x * blockDim.x + threadIdx.x;
    if (i >= MROWS * DTRANK) return;
    int r = i >> 6, c = i & 63;
    float v = g_xdbl[(size_t)r * XDBL + c];
    __nv_bfloat16 h = __float2bfloat16(v);
    __nv_bfloat16 l = __float2bfloat16(v - __bfloat162float(h));
    __nv_bfloat16* o = g_dt2 + (size_t)r * 3 * DTRANK + c;
    o[0] = h; o[DTRANK] = h; o[2 * DTRANK] = l;
}

// ---------------------------------------------------------------------------
// Depthwise causal conv (k=4) + bias + SiLU -> g_xs (fp32) + g_xs2 (A-split)
// ---------------------------------------------------------------------------
__global__ void conv_silu(const float* __restrict__ conv_w,
                          const float* __restrict__ conv_b)
{
    int idx = blockIdx.x * blockDim.x + threadIdx.x;
    if (idx >= MROWS * DINNER) return;
    int d = idx % DINNER;
    int l = (idx / DINNER) % SEQLEN;
    int b = idx / (DINNER * SEQLEN);

    float acc = conv_b[d];
    const float* xi = g_xz + ((size_t)b * SEQLEN) * (2 * DINNER) + d;
#pragma unroll
    for (int j = 0; j < DCONV; j++) {
        int ll = l - (DCONV - 1) + j;
        if (ll >= 0)
            acc += xi[(size_t)ll * (2 * DINNER)] * conv_w[d * DCONV + j];
    }
    float s = acc / (1.f + __expf(-acc));
    g_xs[idx] = s;

    __nv_bfloat16 h = __float2bfloat16(s);
    __nv_bfloat16 lo = __float2bfloat16(s - __bfloat162float(h));
    int row = b * SEQLEN + l;
    __nv_bfloat16* o = g_xs2 + (size_t)row * 3 * DINNER + d;
    o[0] = h; o[DINNER] = h; o[2 * DINNER] = lo;
}

// ---------------------------------------------------------------------------
// Selective scan: warp = 2 channels x 16 state lanes; writes y2 (A-split).
// ---------------------------------------------------------------------------
__global__ void scan_kernel(const float* __restrict__ A_log,
                            const float* __restrict__ Dv)
{
    int gwarp = (blockIdx.x * blockDim.x + threadIdx.x) >> 5;
    int lane  = threadIdx.x & 31;
    int n     = lane & 15;
    int half  = lane >> 4;
    int ch    = gwarp * 2 + half;
    if (ch >= BATCH * DINNER) return;
    int b = ch / DINNER;
    int d = ch % DINNER;

    float a  = -expf(A_log[d * DSTATE + n]);
    float Dd = Dv[d];
    float h  = 0.f;

    const float* dt_p = g_dt   + (size_t)b * SEQLEN * DINNER + d;
    const float* xs_p = g_xs   + (size_t)b * SEQLEN * DINNER + d;
    const float* B_p  = g_xdbl + (size_t)b * SEQLEN * XDBL + DTRANK + n;
    const float* C_p  = B_p + DSTATE;
    const float* z_p  = g_xz   + (size_t)b * SEQLEN * (2 * DINNER) + DINNER + d;
    __nv_bfloat16* y_p = g_y2 + (size_t)b * SEQLEN * 3 * DINNER + d;

    for (int l = 0; l < SEQLEN; l++) {
        float dtv = __ldg(dt_p);
        float xv  = __ldg(xs_p);
        float Bv  = __ldg(B_p);
        float Cv  = __ldg(C_p);

        float dA = __expf(dtv * a);
        h = dA * h + (dtv * xv) * Bv;
        float yv = h * Cv;

        yv += __shfl_xor_sync(0xFFFFFFFFu, yv, 8);
        yv += __shfl_xor_sync(0xFFFFFFFFu, yv, 4);
        yv += __shfl_xor_sync(0xFFFFFFFFu, yv, 2);
        yv += __shfl_xor_sync(0xFFFFFFFFu, yv, 1);

        if (n == 0) {
            float zv = __ldg(z_p);
            float gate = zv / (1.f + __expf(-zv));
            float out = (yv + xv * Dd) * gate;
            __nv_bfloat16 hh = __float2bfloat16(out);
            __nv_bfloat16 ll = __float2bfloat16(out - __bfloat162float(hh));
            y_p[0] = hh; y_p[DINNER] = hh; y_p[2 * DINNER] = ll;
        }

        dt_p += DINNER;
        xs_p += DINNER;
        B_p  += XDBL;
        C_p  += XDBL;
        z_p  += 2 * DINNER;
        y_p  += 3 * DINNER;
    }
}

// ---------------------------------------------------------------------------
extern "C" void kernel_launch(void* const* d_in, const int* in_sizes, int n_in,
                              void* d_out, int out_size)
{
    const float* x         = (const float*)d_in[0];
    const float* in_proj_w = (const float*)d_in[1];
    const float* conv_w    = (const float*)d_in[2];
    const float* conv_b    = (const float*)d_in[3];
    const float* x_proj_w  = (const float*)d_in[4];
    const float* dt_proj_w = (const float*)d_in[5];
    const float* dt_proj_b = (const float*)d_in[6];
    const float* A_log     = (const float*)d_in[7];
    const float* Dv        = (const float*)d_in[8];
    const float* out_proj_w= (const float*)d_in[9];
    float* out = (float*)d_out;

    cudaFuncSetAttribute(gemm_mma, cudaFuncAttributeMaxDynamicSharedMemorySize, GEMM_SMEM);

    float *xz, *xdbl, *dt;
    __nv_bfloat16 *x2, *w1_2, *xs2, *w3_2, *dt2, *w4_2, *y2, *w6_2;
    cudaGetSymbolAddress((void**)&xz,   g_xz);
    cudaGetSymbolAddress((void**)&xdbl, g_xdbl);
    cudaGetSymbolAddress((void**)&dt,   g_dt);
    cudaGetSymbolAddress((void**)&x2,   g_x2);
    cudaGetSymbolAddress((void**)&w1_2, g_w1_2);
    cudaGetSymbolAddress((void**)&xs2,  g_xs2);
    cudaGetSymbolAddress((void**)&w3_2, g_w3_2);
    cudaGetSymbolAddress((void**)&dt2,  g_dt2);
    cudaGetSymbolAddress((void**)&w4_2, g_w4_2);
    cudaGetSymbolAddress((void**)&y2,   g_y2);
    cudaGetSymbolAddress((void**)&w6_2, g_w6_2);

    const int T = 256;
    split_A<<<(MROWS*DMODEL + T-1)/T, T>>>(x, x2, DMODEL, MROWS*DMODEL);
    split_B<<<(2*DINNER*DMODEL + T-1)/T, T>>>(in_proj_w, w1_2, DMODEL, 2*DINNER*DMODEL);
    split_B<<<(XDBL*DINNER + T-1)/T, T>>>(x_proj_w, w3_2, DINNER, XDBL*DINNER);
    split_B<<<(DINNER*DTRANK + T-1)/T, T>>>(dt_proj_w, w4_2, DTRANK, DINNER*DTRANK);
    split_B<<<(DMODEL*DINNER + T-1)/T, T>>>(out_proj_w, w6_2, DINNER, DMODEL*DINNER);

    // 1) xz = x @ in_proj_w^T   (4096 x 4096, K2=3072)
    gemm_mma<<<dim3(2*DINNER/128, MROWS/128), 256, GEMM_SMEM>>>(
        x2, w1_2, xz, 2*DINNER, 3*DMODEL, 2*DINNER, nullptr, 0);

    // 2) conv + SiLU
    conv_silu<<<(MROWS*DINNER + T-1)/T, T>>>(conv_w, conv_b);

    // 3) x_dbl = xs @ x_proj_w^T  (4096 x 160, K2=6144)
    gemm_mma<<<dim3(2, MROWS/128), 256, GEMM_SMEM>>>(
        xs2, w3_2, xdbl, XDBL, 3*DINNER, XDBL, nullptr, 0);

    // 3b) split dt-rank slice
    split_dtrank<<<(MROWS*DTRANK + T-1)/T, T>>>();

    // 4) dt = softplus(x_dbl[:,:64] @ dt_proj_w^T + b)  (4096 x 2048, K2=192)
    gemm_mma<<<dim3(DINNER/128, MROWS/128), 256, GEMM_SMEM>>>(
        dt2, w4_2, dt, DINNER, 3*DTRANK, DINNER, dt_proj_b, 1);

    // 5) selective scan -> y2
    scan_kernel<<<(BATCH*DINNER/2)*32/256, 256>>>(A_log, Dv);

    // 6) out = y @ out_proj_w^T  (4096 x 1024, K2=6144)
    gemm_mma<<<dim3(DMODEL/128, MROWS/128), 256, GEMM_SMEM>>>(
        y2, w6_2, out, DMODEL, 3*DINNER, DMODEL, nullptr, 0);
}

// round 5
// speedup vs baseline: 1.2675x; 1.0370x over previous
#include <cuda_runtime.h>
#include <cuda_bf16.h>
#include <math.h>
#include <stdint.h>

// Problem constants
#define BATCH   2
#define SEQLEN  2048
#define DMODEL  1024
#define DINNER  2048
#define DSTATE  16
#define DCONV   4
#define DTRANK  64
#define XDBL    (DTRANK + 2*DSTATE)   // 160
#define MROWS   (BATCH*SEQLEN)        // 4096

// ---------------------------------------------------------------------------
// Device-global scratch (no allocation allowed)
// ---------------------------------------------------------------------------
__device__ float g_xz  [MROWS * 2*DINNER];   // in_proj output
__device__ float g_xs  [MROWS * DINNER];     // conv+silu output (fp32 for scan)
__device__ float g_xdbl[MROWS * XDBL];       // x_proj output
__device__ float g_dt  [MROWS * DINNER];     // softplus dt (fp32 for scan)
__device__ float g_y   [MROWS * DINNER];     // scan output fp32

// Split-bf16 operands, 64-block-interleaved:
// per 64-col block i: A2 = [hi_i | hi_i | lo_i], B2 = [hi_i | lo_i | hi_i]
__device__ __nv_bfloat16 g_x2  [MROWS * 3*DMODEL];
__device__ __nv_bfloat16 g_w1_2[2*DINNER * 3*DMODEL];
__device__ __nv_bfloat16 g_xs2 [MROWS * 3*DINNER];
__device__ __nv_bfloat16 g_w3_2[XDBL * 3*DINNER];
__device__ __nv_bfloat16 g_dt2 [MROWS * 3*DTRANK];
__device__ __nv_bfloat16 g_w4_2[DINNER * 3*DTRANK];
__device__ __nv_bfloat16 g_y2  [MROWS * 3*DINNER];
__device__ __nv_bfloat16 g_w6_2[DMODEL * 3*DINNER];

// ---------------------------------------------------------------------------
// PTX helpers (baseline ISA: cp.async, ldmatrix, mma.sync)
// ---------------------------------------------------------------------------
__device__ __forceinline__ uint32_t smem_u32(const void* p) {
    uint32_t a;
    asm("{ .reg .u64 t; cvta.to.shared.u64 t, %1; cvt.u32.u64 %0, t; }"
        : "=r"(a) : "l"(p));
    return a;
}

#define CP_ASYNC16(dst, src) \
    asm volatile("cp.async.cg.shared.global [%0], [%1], 16;" :: "r"(dst), "l"(src) : "memory")
#define CP_COMMIT() asm volatile("cp.async.commit_group;" ::: "memory")
#define CP_WAIT2()  asm volatile("cp.async.wait_group 2;" ::: "memory")

#define LDSM4(r, addr) \
    asm volatile("ldmatrix.sync.aligned.m8n8.x4.shared.b16 {%0,%1,%2,%3}, [%4];" \
        : "=r"((r)[0]), "=r"((r)[1]), "=r"((r)[2]), "=r"((r)[3]) : "r"(addr))

#define MMA16816(c, a, b) \
    asm volatile("mma.sync.aligned.m16n8k16.row.col.f32.bf16.bf16.f32 " \
        "{%0,%1,%2,%3}, {%4,%5,%6,%7}, {%8,%9}, {%0,%1,%2,%3};" \
        : "+f"((c)[0]), "+f"((c)[1]), "+f"((c)[2]), "+f"((c)[3]) \
        : "r"((a)[0]), "r"((a)[1]), "r"((a)[2]), "r"((a)[3]), \
          "r"((b)[0]), "r"((b)[1]))

// ---------------------------------------------------------------------------
// Tensor-core GEMM: C[M, Nact] = A2[M, K2] * B2[Nact, K2]^T (bf16 in, fp32 out)
// Block tile 128x128, BK=64 (128B rows), 8 warps = 2(M) x 4(N), warp 64x32.
// 3-stage cp.async pipeline, swizzled smem, ldmatrix + mma.sync.
// mode 0: plain store; mode 1: softplus(v + bias[col]).
// Requirements: M % 128 == 0, K2 % 64 == 0.
// ---------------------------------------------------------------------------
#define STAGE_B 32768
#define GEMM_SMEM (3 * STAGE_B)

__global__ void __launch_bounds__(256, 2)
gemm_mma(const __nv_bfloat16* __restrict__ A2,
         const __nv_bfloat16* __restrict__ B2,
         float* __restrict__ C, int ldc, int K2, int Nact,
         const float* __restrict__ bias, int mode)
{
    extern __shared__ char smem[];
    const uint32_t sb = smem_u32(smem);
    const int tid  = threadIdx.x;
    const int wid  = tid >> 5;
    const int lane = tid & 31;
    const int wm   = wid >> 2;       // 0..1
    const int wn   = wid & 3;        // 0..3
    const int mBase = blockIdx.y * 128;
    const int nBase = blockIdx.x * 128;

    // per-thread cp.async source: row r = tid>>1, half = tid&1 (64B each)
    const int r    = tid >> 1;
    const int half = tid & 1;
    const __nv_bfloat16* aSrcRow = A2 + (size_t)(mBase + r) * K2;
    int brow = nBase + r; if (brow >= Nact) brow = Nact - 1;
    const __nv_bfloat16* bSrcRow = B2 + (size_t)brow * K2;
    const uint32_t dstRowOff = (uint32_t)r * 128;
    const uint32_t rxor = (uint32_t)(r & 7) << 4;

    const int nch = K2 >> 6;

#define ISSUE(c, buf) do {                                                    \
    const char* as = (const char*)aSrcRow + (size_t)(c) * 128 + half * 64;    \
    const char* bs = (const char*)bSrcRow + (size_t)(c) * 128 + half * 64;    \
    uint32_t abuf = sb + (uint32_t)(buf) * STAGE_B;                           \
    uint32_t bbuf = abuf + 16384;                                             \
    _Pragma("unroll")                                                         \
    for (int u = 0; u < 4; u++) {                                             \
        uint32_t boff = (uint32_t)(half * 64 + u * 16) ^ rxor;                \
        CP_ASYNC16(abuf + dstRowOff + boff, as + u * 16);                     \
        CP_ASYNC16(bbuf + dstRowOff + boff, bs + u * 16);                     \
    }                                                                         \
} while (0)

    float acc[4][4][4];
#pragma unroll
    for (int i = 0; i < 4; i++)
#pragma unroll
        for (int j = 0; j < 4; j++)
#pragma unroll
            for (int k = 0; k < 4; k++) acc[i][j][k] = 0.f;

    const uint32_t lrow  = lane & 15;
    const uint32_t lsel  = (lane >> 4) * 16;          // k-half select (bytes)
    const uint32_t lxor  = (uint32_t)(lane & 7) << 4; // swizzle for addressed row

    // prologue: fill 3 stages
    ISSUE(0, 0); CP_COMMIT();
    if (nch > 1) ISSUE(1, 1);
    CP_COMMIT();
    if (nch > 2) ISSUE(2, 2);
    CP_COMMIT();

    int buf = 0;
    for (int c = 0; c < nch; c++) {
        CP_WAIT2();                 // group c complete
        __syncthreads();

        const uint32_t abuf = sb + (uint32_t)buf * STAGE_B;
        const uint32_t bbuf = abuf + 16384;
        const uint32_t aRow = abuf + (wm * 64 + lrow) * 128;
        const uint32_t bRow = bbuf + (wn * 32 + lrow) * 128;

#pragma unroll
        for (int s = 0; s < 4; s++) {
            const uint32_t kb = ((uint32_t)(s * 32) + lsel) ^ lxor;
            uint32_t aF[4][4];
            uint32_t bF[4][2];
#pragma unroll
            for (int mt = 0; mt < 4; mt++)
                LDSM4(aF[mt], aRow + mt * 2048 + kb);
#pragma unroll
            for (int nh = 0; nh < 2; nh++) {
                uint32_t t[4];
                LDSM4(t, bRow + nh * 2048 + kb);
                // x4 order: t0=(n0-7,kL) t1=(n8-15,kL) t2=(n0-7,kH) t3=(n8-15,kH)
                bF[nh * 2 + 0][0] = t[0]; bF[nh * 2 + 0][1] = t[2];
                bF[nh * 2 + 1][0] = t[1]; bF[nh * 2 + 1][1] = t[3];
            }
#pragma unroll
            for (int mt = 0; mt < 4; mt++)
#pragma unroll
                for (int nt = 0; nt < 4; nt++)
                    MMA16816(acc[mt][nt], aF[mt], bF[nt]);
        }
        __syncthreads();            // all warps done with `buf` before refill
        if (c + 3 < nch) ISSUE(c + 3, buf);
        CP_COMMIT();
        buf = (buf == 2) ? 0 : buf + 1;
    }

    // Epilogue
    const int er0 = mBase + wm * 64 + (lane >> 2);
    const int ec0 = nBase + wn * 32 + (lane & 3) * 2;
#pragma unroll
    for (int mt = 0; mt < 4; mt++) {
#pragma unroll
        for (int nt = 0; nt < 4; nt++) {
            int col = ec0 + nt * 8;
#pragma unroll
            for (int h = 0; h < 2; h++) {
                int row = er0 + mt * 16 + h * 8;
                float v0 = acc[mt][nt][h * 2 + 0];
                float v1 = acc[mt][nt][h * 2 + 1];
                if (mode == 1) {
                    if (col < Nact) {
                        v0 += bias[col];
                        v0 = (v0 > 20.f) ? v0 : log1pf(expf(v0));
                    }
                    if (col + 1 < Nact) {
                        v1 += bias[col + 1];
                        v1 = (v1 > 20.f) ? v1 : log1pf(expf(v1));
                    }
                }
                float* cp = C + (size_t)row * ldc + col;
                if (col + 1 < Nact) {
                    *(float2*)cp = make_float2(v0, v1);
                } else if (col < Nact) {
                    cp[0] = v0;
                }
            }
        }
    }
#undef ISSUE
}

// ---------------------------------------------------------------------------
// Split kernels: fp32 -> 64-block-interleaved bf16 layouts, fully coalesced.
// Each thread handles 2 consecutive elements (float2 read, 3x bf16x2 store).
// A-type segment order [hi|hi|lo], B-type [hi|lo|hi].
// ---------------------------------------------------------------------------
__device__ __forceinline__ void split2(float2 v, __nv_bfloat162& hh, __nv_bfloat162& ll)
{
    __nv_bfloat16 h0 = __float2bfloat16(v.x);
    __nv_bfloat16 h1 = __float2bfloat16(v.y);
    __nv_bfloat16 l0 = __float2bfloat16(v.x - __bfloat162float(h0));
    __nv_bfloat16 l1 = __float2bfloat16(v.y - __bfloat162float(h1));
    hh = __nv_bfloat162(h0, h1);
    ll = __nv_bfloat162(l0, l1);
}

__global__ void split_A(const float* __restrict__ in, __nv_bfloat16* __restrict__ out,
                        int K, int total2)   // total2 = R*K/2
{
    int i = blockIdx.x * blockDim.x + threadIdx.x;
    if (i >= total2) return;
    int kh = K >> 1;
    int r = i / kh, c = (i - r * kh) * 2;
    __nv_bfloat162 hh, ll;
    split2(*(const float2*)(in + (size_t)r * K + c), hh, ll);
    __nv_bfloat162* o = (__nv_bfloat162*)(out + (size_t)r * 3 * K + (c >> 6) * 192 + (c & 63));
    o[0] = hh; o[32] = hh; o[64] = ll;
}

__global__ void split_B(const float* __restrict__ in, __nv_bfloat16* __restrict__ out,
                        int K, int total2)
{
    int i = blockIdx.x * blockDim.x + threadIdx.x;
    if (i >= total2) return;
    int kh = K >> 1;
    int r = i / kh, c = (i - r * kh) * 2;
    __nv_bfloat162 hh, ll;
    split2(*(const float2*)(in + (size_t)r * K + c), hh, ll);
    __nv_bfloat162* o = (__nv_bfloat162*)(out + (size_t)r * 3 * K + (c >> 6) * 192 + (c & 63));
    o[0] = hh; o[32] = ll; o[64] = hh;
}

// x_dbl[:, :DTRANK] (row stride XDBL) -> g_dt2 [MROWS, 192] A-type (K=64, 1 block)
__global__ void split_dtrank()
{
    int i = blockIdx.x * blockDim.x + threadIdx.x;
    if (i >= MROWS * 32) return;
    int r = i >> 5, c = (i & 31) * 2;
    __nv_bfloat162 hh, ll;
    split2(*(const float2*)(g_xdbl + (size_t)r * XDBL + c), hh, ll);
    __nv_bfloat162* o = (__nv_bfloat162*)(g_dt2 + (size_t)r * 192 + c);
    o[0] = hh; o[32] = hh; o[64] = ll;
}

// ---------------------------------------------------------------------------
// Depthwise causal conv (k=4) + bias + SiLU -> g_xs (fp32) + g_xs2 (A-split)
// Thread handles 2 consecutive d -> coalesced bf16x2 stores.
// ---------------------------------------------------------------------------
__global__ void conv_silu(const float* __restrict__ conv_w,
                          const float* __restrict__ conv_b)
{
    int i = blockIdx.x * blockDim.x + threadIdx.x;       // over MROWS*DINNER/2
    if (i >= MROWS * DINNER / 2) return;
    int dh = i % (DINNER / 2);
    int row = i / (DINNER / 2);
    int d = dh * 2;
    int l = row % SEQLEN;
    int b = row / SEQLEN;

    float acc0 = conv_b[d];
    float acc1 = conv_b[d + 1];
    const float* xi = g_xz + ((size_t)b * SEQLEN) * (2 * DINNER) + d;
    const float* w0 = conv_w + d * DCONV;
    const float* w1 = conv_w + (d + 1) * DCONV;
#pragma unroll
    for (int j = 0; j < DCONV; j++) {
        int ll = l - (DCONV - 1) + j;
        if (ll >= 0) {
            float2 xv = *(const float2*)(xi + (size_t)ll * (2 * DINNER));
            acc0 += xv.x * w0[j];
            acc1 += xv.y * w1[j];
        }
    }
    float s0 = acc0 / (1.f + __expf(-acc0));
    float s1 = acc1 / (1.f + __expf(-acc1));
    *(float2*)(g_xs + (size_t)row * DINNER + d) = make_float2(s0, s1);

    __nv_bfloat162 hh, ll2;
    split2(make_float2(s0, s1), hh, ll2);
    __nv_bfloat162* o = (__nv_bfloat162*)(g_xs2 + (size_t)row * 3 * DINNER + (d >> 6) * 192 + (d & 63));
    o[0] = hh; o[32] = hh; o[64] = ll2;
}

// ---------------------------------------------------------------------------
// Selective scan: warp = 2 channels x 16 state lanes; writes fp32 g_y.
// ---------------------------------------------------------------------------
__global__ void scan_kernel(const float* __restrict__ A_log,
                            const float* __restrict__ Dv)
{
    int gwarp = (blockIdx.x * blockDim.x + threadIdx.x) >> 5;
    int lane  = threadIdx.x & 31;
    int n     = lane & 15;
    int half  = lane >> 4;
    int ch    = gwarp * 2 + half;
    if (ch >= BATCH * DINNER) return;
    int b = ch / DINNER;
    int d = ch % DINNER;

    float a  = -expf(A_log[d * DSTATE + n]);
    float Dd = Dv[d];
    float h  = 0.f;

    const float* dt_p = g_dt   + (size_t)b * SEQLEN * DINNER + d;
    const float* xs_p = g_xs   + (size_t)b * SEQLEN * DINNER + d;
    const float* B_p  = g_xdbl + (size_t)b * SEQLEN * XDBL + DTRANK + n;
    const float* C_p  = B_p + DSTATE;
    const float* z_p  = g_xz   + (size_t)b * SEQLEN * (2 * DINNER) + DINNER + d;
    float*       y_p  = g_y    + (size_t)b * SEQLEN * DINNER + d;

    for (int l = 0; l < SEQLEN; l++) {
        float dtv = __ldg(dt_p);
        float xv  = __ldg(xs_p);
        float Bv  = __ldg(B_p);
        float Cv  = __ldg(C_p);

        float dA = __expf(dtv * a);
        h = dA * h + (dtv * xv) * Bv;
        float yv = h * Cv;

        yv += __shfl_xor_sync(0xFFFFFFFFu, yv, 8);
        yv += __shfl_xor_sync(0xFFFFFFFFu, yv, 4);
        yv += __shfl_xor_sync(0xFFFFFFFFu, yv, 2);
        yv += __shfl_xor_sync(0xFFFFFFFFu, yv, 1);

        if (n == 0) {
            float zv = __ldg(z_p);
            float gate = zv / (1.f + __expf(-zv));
            *y_p = (yv + xv * Dd) * gate;
        }

        dt_p += DINNER;
        xs_p += DINNER;
        B_p  += XDBL;
        C_p  += XDBL;
        z_p  += 2 * DINNER;
        y_p  += DINNER;
    }
}

// ---------------------------------------------------------------------------
extern "C" void kernel_launch(void* const* d_in, const int* in_sizes, int n_in,
                              void* d_out, int out_size)
{
    const float* x         = (const float*)d_in[0];
    const float* in_proj_w = (const float*)d_in[1];
    const float* conv_w    = (const float*)d_in[2];
    const float* conv_b    = (const float*)d_in[3];
    const float* x_proj_w  = (const float*)d_in[4];
    const float* dt_proj_w = (const float*)d_in[5];
    const float* dt_proj_b = (const float*)d_in[6];
    const float* A_log     = (const float*)d_in[7];
    const float* Dv        = (const float*)d_in[8];
    const float* out_proj_w= (const float*)d_in[9];
    float* out = (float*)d_out;

    cudaFuncSetAttribute(gemm_mma, cudaFuncAttributeMaxDynamicSharedMemorySize, GEMM_SMEM);

    float *xz, *xdbl, *dt, *y;
    __nv_bfloat16 *x2, *w1_2, *xs2, *w3_2, *dt2, *w4_2, *y2, *w6_2;
    cudaGetSymbolAddress((void**)&xz,   g_xz);
    cudaGetSymbolAddress((void**)&xdbl, g_xdbl);
    cudaGetSymbolAddress((void**)&dt,   g_dt);
    cudaGetSymbolAddress((void**)&y,    g_y);
    cudaGetSymbolAddress((void**)&x2,   g_x2);
    cudaGetSymbolAddress((void**)&w1_2, g_w1_2);
    cudaGetSymbolAddress((void**)&xs2,  g_xs2);
    cudaGetSymbolAddress((void**)&w3_2, g_w3_2);
    cudaGetSymbolAddress((void**)&dt2,  g_dt2);
    cudaGetSymbolAddress((void**)&w4_2, g_w4_2);
    cudaGetSymbolAddress((void**)&y2,   g_y2);
    cudaGetSymbolAddress((void**)&w6_2, g_w6_2);

    const int T = 256;
    split_A<<<(MROWS*DMODEL/2 + T-1)/T, T>>>(x, x2, DMODEL, MROWS*DMODEL/2);
    split_B<<<(2*DINNER*DMODEL/2 + T-1)/T, T>>>(in_proj_w, w1_2, DMODEL, 2*DINNER*DMODEL/2);
    split_B<<<(XDBL*DINNER/2 + T-1)/T, T>>>(x_proj_w, w3_2, DINNER, XDBL*DINNER/2);
    split_B<<<(DINNER*DTRANK/2 + T-1)/T, T>>>(dt_proj_w, w4_2, DTRANK, DINNER*DTRANK/2);
    split_B<<<(DMODEL*DINNER/2 + T-1)/T, T>>>(out_proj_w, w6_2, DINNER, DMODEL*DINNER/2);

    // 1) xz = x @ in_proj_w^T   (4096 x 4096, K2=3072)
    gemm_mma<<<dim3(2*DINNER/128, MROWS/128), 256, GEMM_SMEM>>>(
        x2, w1_2, xz, 2*DINNER, 3*DMODEL, 2*DINNER, nullptr, 0);

    // 2) conv + SiLU
    conv_silu<<<(MROWS*DINNER/2 + T-1)/T, T>>>(conv_w, conv_b);

    // 3) x_dbl = xs @ x_proj_w^T  (4096 x 160, K2=6144)
    gemm_mma<<<dim3(2, MROWS/128), 256, GEMM_SMEM>>>(
        xs2, w3_2, xdbl, XDBL, 3*DINNER, XDBL, nullptr, 0);

    // 3b) split dt-rank slice
    split_dtrank<<<(MROWS*32 + T-1)/T, T>>>();

    // 4) dt = softplus(x_dbl[:,:64] @ dt_proj_w^T + b)  (4096 x 2048, K2=192)
    gemm_mma<<<dim3(DINNER/128, MROWS/128), 256, GEMM_SMEM>>>(
        dt2, w4_2, dt, DINNER, 3*DTRANK, DINNER, dt_proj_b, 1);

    // 5) selective scan -> y (fp32)
    scan_kernel<<<(BATCH*DINNER/2)*32/256, 256>>>(A_log, Dv);

    // 5b) split y (coalesced)
    split_A<<<(MROWS*DINNER/2 + T-1)/T, T>>>(y, y2, DINNER, MROWS*DINNER/2);

    // 6) out = y @ out_proj_w^T  (4096 x 1024, K2=6144)
    gemm_mma<<<dim3(DMODEL/128, MROWS/128), 256, GEMM_SMEM>>>(
        y2, w6_2, out, DMODEL, 3*DINNER, DMODEL, nullptr, 0);
}